// round 1
// baseline (speedup 1.0000x reference)
#include <cuda_runtime.h>
#include <math.h>

#define HW 16384

// Scratch (module-load allocated, legal per harness rules)
__device__ float g_om [4 * 216 * HW];   // offset/mask conv output
__device__ float g_em1[4 *  64 * HW];   // em intermediate
__device__ float g_em [4 *  72 * HW];   // em mask (sigmoid)

// ---------------------------------------------------------------------------
// Generic direct 3x3 conv, stride 1, pad 1, H=W=128, NCHW fp32.
// Block: 256 threads -> 32x32 output tile, each thread a 2x2 micro-tile
// (strided by 16 for conflict-free LDS), 8 output channels in registers.
// Input channels streamed through smem in chunks of 4.
// ACT: 0 = none, 1 = leaky(0.1), 2 = sigmoid
// Supports channel-concat input via (in1, cin1) + in2.
// ---------------------------------------------------------------------------
template <int ACT>
__global__ __launch_bounds__(256) void conv3x3_kernel(
    const float* __restrict__ in1, const float* __restrict__ in2,
    int cin1, int cin,
    const float* __restrict__ wgt, const float* __restrict__ bias,
    float* __restrict__ out, int cout)
{
    __shared__ float s_in[4][34][36];
    __shared__ float s_w[8][4][9];

    const int tid = threadIdx.x;
    const int co_tiles = cout >> 3;
    const int b   = blockIdx.z / co_tiles;
    const int co0 = (blockIdx.z % co_tiles) << 3;
    const int h0  = blockIdx.y * 32;
    const int w0  = blockIdx.x * 32;
    const int ty  = tid >> 4;
    const int tx  = tid & 15;

    float acc[2][2][8];
#pragma unroll
    for (int sy = 0; sy < 2; sy++)
#pragma unroll
        for (int sx = 0; sx < 2; sx++)
#pragma unroll
            for (int o = 0; o < 8; o++) acc[sy][sx][o] = 0.f;

    const int nchunks = cin >> 2;
    for (int cb = 0; cb < nchunks; cb++) {
        const int c0 = cb << 2;
        // stage 34x34x4 input tile (zero-padded borders)
        for (int i = tid; i < 4 * 34 * 34; i += 256) {
            int ci = i / 1156;
            int r  = i - ci * 1156;
            int yy = r / 34;
            int xx = r - yy * 34;
            int gh = h0 - 1 + yy;
            int gw = w0 - 1 + xx;
            int c  = c0 + ci;
            float v = 0.f;
            if (gh >= 0 && gh < 128 && gw >= 0 && gw < 128) {
                const float* p = (c < cin1)
                    ? (in1 + ((size_t)b * cin1 + c) * HW)
                    : (in2 + ((size_t)b * (cin - cin1) + (c - cin1)) * HW);
                v = p[gh * 128 + gw];
            }
            s_in[ci][yy][xx] = v;
        }
        // stage 8co x 4ci x 9 weights
        for (int i = tid; i < 8 * 4 * 9; i += 256) {
            int o  = i / 36;
            int r  = i - o * 36;
            int ci = r / 9;
            int k  = r - ci * 9;
            s_w[o][ci][k] = wgt[((size_t)(co0 + o) * cin + (c0 + ci)) * 9 + k];
        }
        __syncthreads();

#pragma unroll
        for (int ci = 0; ci < 4; ci++) {
#pragma unroll
            for (int ky = 0; ky < 3; ky++) {
#pragma unroll
                for (int kx = 0; kx < 3; kx++) {
                    float wv[8];
#pragma unroll
                    for (int o = 0; o < 8; o++) wv[o] = s_w[o][ci][ky * 3 + kx];
#pragma unroll
                    for (int sy = 0; sy < 2; sy++) {
#pragma unroll
                        for (int sx = 0; sx < 2; sx++) {
                            float v = s_in[ci][ty + 16 * sy + ky][tx + 16 * sx + kx];
#pragma unroll
                            for (int o = 0; o < 8; o++)
                                acc[sy][sx][o] += v * wv[o];
                        }
                    }
                }
            }
        }
        __syncthreads();
    }

#pragma unroll
    for (int o = 0; o < 8; o++) {
        float bs = bias[co0 + o];
#pragma unroll
        for (int sy = 0; sy < 2; sy++) {
#pragma unroll
            for (int sx = 0; sx < 2; sx++) {
                float v = acc[sy][sx][o] + bs;
                if (ACT == 1) v = (v >= 0.f) ? v : 0.1f * v;
                if (ACT == 2) v = 1.f / (1.f + expf(-v));
                out[((size_t)b * cout + co0 + o) * HW
                    + (h0 + ty + 16 * sy) * 128 + (w0 + tx + 16 * sx)] = v;
            }
        }
    }
}

// ---------------------------------------------------------------------------
// Fused dual modulated deformable conv (DCNv2), stride 1, pad 1.
// offsets/mask come straight from g_om:
//   dy = om[b, 2*(g*9+kk)], dx = om[b, 2*(g*9+kk)+1], mx = sigmoid(om[b,144+g*9+kk])
// second mask from g_em[b, g*9+kk]. Both outputs share offsets + w_dc.
// Thread per (b,g,h,w); 8 out-channels x 2 tensors in registers.
// ---------------------------------------------------------------------------
__global__ __launch_bounds__(256) void deform_kernel(
    const float* __restrict__ x, const float* __restrict__ s,
    const float* __restrict__ w_dc, const float* __restrict__ b_dc,
    float* __restrict__ out)
{
    __shared__ float s_w[8][8][9];  // [o][c][kk] for this group

    const int tid = threadIdx.x;
    const int b = blockIdx.z >> 3;
    const int g = blockIdx.z & 7;
    const int ty = tid >> 4;
    const int tx = tid & 15;
    const int h  = blockIdx.y * 16 + ty;
    const int wp = blockIdx.x * 16 + tx;

    for (int i = tid; i < 576; i += 256)
        ((float*)s_w)[i] = w_dc[(size_t)g * 576 + i];
    __syncthreads();

    const int pix = h * 128 + wp;
    const float* om_b = g_om + (size_t)b * 216 * HW;
    const float* em_b = g_em + (size_t)b * 72 * HW;
    const float* xb = x + ((size_t)b * 64 + g * 8) * HW;
    const float* sb = s + ((size_t)b * 64 + g * 8) * HW;

    float accx[8], accs[8];
#pragma unroll
    for (int o = 0; o < 8; o++) { accx[o] = 0.f; accs[o] = 0.f; }

    for (int kk = 0; kk < 9; kk++) {
        const int mch = g * 9 + kk;
        float dy   = om_b[(size_t)(2 * mch) * HW + pix];
        float dx   = om_b[(size_t)(2 * mch + 1) * HW + pix];
        float mraw = om_b[(size_t)(144 + mch) * HW + pix];
        float mx = 1.f / (1.f + expf(-mraw));
        float me = em_b[(size_t)mch * HW + pix];

        float py = (float)(h - 1 + kk / 3) + dy;
        float px = (float)(wp - 1 + kk % 3) + dx;
        float y0f = floorf(py), x0f = floorf(px);
        int y0 = (int)y0f, x0 = (int)x0f;
        float ly = py - y0f, lx = px - x0f;
        int y1 = y0 + 1, x1 = x0 + 1;

        float vy0 = (y0 >= 0 && y0 < 128) ? 1.f : 0.f;
        float vy1 = (y1 >= 0 && y1 < 128) ? 1.f : 0.f;
        float vx0 = (x0 >= 0 && x0 < 128) ? 1.f : 0.f;
        float vx1 = (x1 >= 0 && x1 < 128) ? 1.f : 0.f;

        float w00 = (1.f - ly) * (1.f - lx) * vy0 * vx0;
        float w01 = (1.f - ly) * lx         * vy0 * vx1;
        float w10 = ly * (1.f - lx)         * vy1 * vx0;
        float w11 = ly * lx                 * vy1 * vx1;

        int cy0 = min(max(y0, 0), 127), cy1 = min(max(y1, 0), 127);
        int cx0 = min(max(x0, 0), 127), cx1 = min(max(x1, 0), 127);
        int i00 = cy0 * 128 + cx0, i01 = cy0 * 128 + cx1;
        int i10 = cy1 * 128 + cx0, i11 = cy1 * 128 + cx1;

#pragma unroll
        for (int c = 0; c < 8; c++) {
            const float* xp = xb + (size_t)c * HW;
            const float* sp = sb + (size_t)c * HW;
            float vx = w00 * xp[i00] + w01 * xp[i01] + w10 * xp[i10] + w11 * xp[i11];
            float vs = w00 * sp[i00] + w01 * sp[i01] + w10 * sp[i10] + w11 * sp[i11];
            float ax  = vx * mx;
            float as_ = vs * me;
#pragma unroll
            for (int o = 0; o < 8; o++) {
                float wv = s_w[o][c][kk];
                accx[o] += ax * wv;
                accs[o] += as_ * wv;
            }
        }
    }

#pragma unroll
    for (int o = 0; o < 8; o++) {
        float bs = b_dc[g * 8 + o];
        size_t oidx = ((size_t)b * 64 + g * 8 + o) * HW + pix;
        out[oidx] = accx[o] + bs;
        out[(size_t)4 * 64 * HW + oidx] = accs[o] + bs;
    }
}

extern "C" void kernel_launch(void* const* d_in, const int* in_sizes, int n_in,
                              void* d_out, int out_size)
{
    const float* x     = (const float*)d_in[0];
    const float* shf   = (const float*)d_in[1];
    const float* off   = (const float*)d_in[2];
    const float* w_om  = (const float*)d_in[3];
    const float* b_om  = (const float*)d_in[4];
    const float* w_em1 = (const float*)d_in[5];
    const float* b_em1 = (const float*)d_in[6];
    const float* w_em2 = (const float*)d_in[7];
    const float* b_em2 = (const float*)d_in[8];
    const float* w_dc  = (const float*)d_in[9];
    const float* b_dc  = (const float*)d_in[10];
    float* out = (float*)d_out;

    float *p_om, *p_em1, *p_em;
    cudaGetSymbolAddress((void**)&p_om,  g_om);
    cudaGetSymbolAddress((void**)&p_em1, g_em1);
    cudaGetSymbolAddress((void**)&p_em,  g_em);

    // om = conv3x3(offset_feat) : 64 -> 216
    conv3x3_kernel<0><<<dim3(4, 4, 4 * 27), 256>>>(
        off, nullptr, 64, 64, w_om, b_om, p_om, 216);

    // em1 = leaky(conv3x3(concat(share, offset_feat))) : 128 -> 64
    conv3x3_kernel<1><<<dim3(4, 4, 4 * 8), 256>>>(
        shf, off, 64, 128, w_em1, b_em1, p_em1, 64);

    // em = sigmoid(conv3x3(em1)) : 64 -> 72
    conv3x3_kernel<2><<<dim3(4, 4, 4 * 9), 256>>>(
        p_em1, nullptr, 64, 64, w_em2, b_em2, p_em, 72);

    // both deformable convs fused (shared offsets + weights)
    deform_kernel<<<dim3(8, 8, 32), 256>>>(x, shf, w_dc, b_dc, out);
}